// round 9
// baseline (speedup 1.0000x reference)
#include <cuda_runtime.h>
#include <math.h>

namespace {
constexpr int B = 16, T = 100, N = 128, D = 3;
constexpr int FRAMES = B * T;                 // 1600
constexpr int NIT = 2;                        // frames per block
constexpr int BLOCKS = FRAMES / NIT;          // 800
constexpr int FD = N * D;                     // 384 floats per frame
constexpr int F4 = FD / 4;                    // 96 float4 per frame
constexpr float MIN_DIST = 0.05f;
constexpr float R2 = MIN_DIST * MIN_DIST;     // 0.0025
constexpr float R2_GUARD = R2 + 1e-4f;        // slack for expansion error
constexpr int EXT = 192;                      // 128 + 64 wrap replica
}

__device__ float g_pen[BLOCKS];
__device__ float g_work[BLOCKS];
__device__ float g_stab[BLOCKS];
__device__ float g_ke0[BLOCKS];
__device__ float g_ke1[BLOCKS];
__device__ unsigned int g_count;              // zero-init; self-resetting

__global__ __launch_bounds__(256) void fused_kernel(
    const float* __restrict__ traj,
    const float* __restrict__ vel,
    const float* __restrict__ frc,
    float* __restrict__ out)
{
    const int tid = threadIdx.x;
    const int f0  = blockIdx.x * NIT;

    __shared__ __align__(16) float4 sP[NIT][EXT];        // (x,y,z,|p|^2)+replica
    __shared__ __align__(16) float  sT[(NIT + 1) * FD];  // raw traj: 3 frames
    __shared__ __align__(16) float  sF[NIT * FD];        // raw frc: 2 frames

    // ========== phase 1: single bulk LDG burst (max MLP) ==========
    {
        const float4* t4 = reinterpret_cast<const float4*>(traj);
        const float4* f4 = reinterpret_cast<const float4*>(frc);
        float4* dT = reinterpret_cast<float4*>(sT);
        float4* dF = reinterpret_cast<float4*>(sF);
        const int baseT = f0 * F4;
        // traj: 3 frames = 288 float4 (guard global end for lookahead)
        {
            int idx = tid;
            float4 v = (baseT + idx < FRAMES * F4) ? t4[baseT + idx]
                                                   : make_float4(0, 0, 0, 0);
            dT[idx] = v;
            idx = tid + 256;
            if (idx < (NIT + 1) * F4) {
                float4 w = (baseT + idx < FRAMES * F4) ? t4[baseT + idx]
                                                       : make_float4(0, 0, 0, 0);
                dT[idx] = w;
            }
        }
        // frc: 2 frames = 192 float4
        if (tid < NIT * F4) dF[tid] = f4[baseT + tid];
    }
    __syncthreads();

    // ========== phase 2: build float4 frames + cheap terms ==========
    float penacc = 0.f, wrkacc = 0.f, stabacc = 0.f, ke0acc = 0.f, ke1acc = 0.f;
    {
        const int fl = tid >> 7;               // local frame 0..1
        const int p  = tid & 127;              // point index
        const int t  = (f0 + fl) % T;

        const float x = sT[fl * FD + 3 * p];
        const float y = sT[fl * FD + 3 * p + 1];
        const float z = sT[fl * FD + 3 * p + 2];
        const float w = x * x + y * y + z * z;
        float4 v4 = make_float4(x, y, z, w);
        sP[fl][p] = v4;
        if (p < 64) sP[fl][128 + p] = v4;

        if (t < T - 1) {                       // work term from staged data
            const float nx = sT[(fl + 1) * FD + 3 * p];
            const float ny = sT[(fl + 1) * FD + 3 * p + 1];
            const float nz = sT[(fl + 1) * FD + 3 * p + 2];
            const float fx = sF[fl * FD + 3 * p];
            const float fy = sF[fl * FD + 3 * p + 1];
            const float fz = sF[fl * FD + 3 * p + 2];
            wrkacc = fx * (nx - x) + fy * (ny - y) + fz * (nz - z);
        }
        if (t == 0 || t >= T - 5) {            // rare boundary-frame vel terms
            const float* pv = vel + (size_t)(f0 + fl) * FD + 3 * p;
            float vx = pv[0], vy = pv[1], vz = pv[2];
            float v2 = vx * vx + vy * vy + vz * vz;
            if (t >= T - 5) {
                stabacc = sqrtf(v2);
                if (t == T - 1) ke1acc = 0.5f * v2;
            } else {
                ke0acc = 0.5f * v2;
            }
        }
    }
    __syncthreads();

    // ========== phase 3: 2-row blocked mainloop, batched LDS ==========
    {
        const int fh = tid >> 7;               // frame this thread works on
        const int u  = tid & 127;
        const int m  = u & 63;                 // row-pair index
        const int h  = u >> 6;                 // j-half
        const int r0 = 2 * m;
        const int jb = 1 + 32 * h;             // first owned j
        const float4* P = sP[fh];
        const float4* C = P + r0 + jb;         // columns c0 .. c0+32

        const float4 A  = P[r0];
        const float4 Bv = P[r0 + 1];
        const float w0 = A.w,  ax = -2.0f * A.x,  ay = -2.0f * A.y,  az = -2.0f * A.z;
        const float w1 = Bv.w, bx = -2.0f * Bv.x, by = -2.0f * Bv.y, bz = -2.0f * Bv.z;

        float acc0 = 1e30f, acc1 = 1e30f, acc2 = 1e30f, acc3 = 1e30f;

        // 4 batches of 8 columns (k = 0..31), loads forced ahead of math
        #pragma unroll
        for (int bq = 0; bq < 4; ++bq) {
            float4 q[8];
            #pragma unroll
            for (int e = 0; e < 8; ++e) q[e] = C[8 * bq + e];
            #pragma unroll
            for (int e = 0; e < 8; ++e) {
                const int k = 8 * bq + e;
                float s0 = w0 + q[e].w;
                s0 = fmaf(ax, q[e].x, s0);
                s0 = fmaf(ay, q[e].y, s0);
                s0 = fmaf(az, q[e].z, s0);
                float s1 = w1 + q[e].w;
                s1 = fmaf(bx, q[e].x, s1);
                s1 = fmaf(by, q[e].y, s1);
                s1 = fmaf(bz, q[e].z, s1);
                if (k == 0) {
                    acc0 = fminf(acc0, s0);    // row0 only (row1 would be self)
                } else if (e & 1) {
                    acc1 = fminf(acc1, s0); acc3 = fminf(acc3, s1);
                } else {
                    acc0 = fminf(acc0, s0); acc2 = fminf(acc2, s1);
                }
            }
        }
        {   // k = 32: row1 only
            float4 q = C[32];
            float s1 = w1 + q.w;
            s1 = fmaf(bx, q.x, s1);
            s1 = fmaf(by, q.y, s1);
            s1 = fmaf(bz, q.z, s1);
            acc2 = fminf(acc2, s1);
        }
        const float dmin = fminf(fminf(acc0, acc1), fminf(acc2, acc3));

        // rare exact slow path over owned pairs
        if (dmin < R2_GUARD) {
            #pragma unroll
            for (int rr = 0; rr < 2; ++rr) {
                const int r = r0 + rr;
                const float px = P[r].x, py = P[r].y, pz = P[r].z;
                for (int kk = 0; kk < 32; ++kk) {
                    const int j = jb + kk;
                    const int k = r + j;
                    float dx = px - P[k].x, dy = py - P[k].y, dz = pz - P[k].z;
                    float e2 = dx * dx + dy * dy + dz * dz;
                    if (e2 < R2) {
                        float c = MIN_DIST - sqrtf(e2);
                        penacc += (j == 64) ? 0.5f * c : c;
                    }
                }
            }
        }
    }

    // ========== block reduction of 5 accumulators ==========
    #pragma unroll
    for (int off = 16; off > 0; off >>= 1) {
        penacc  += __shfl_down_sync(0xffffffffu, penacc,  off);
        wrkacc  += __shfl_down_sync(0xffffffffu, wrkacc,  off);
        stabacc += __shfl_down_sync(0xffffffffu, stabacc, off);
        ke0acc  += __shfl_down_sync(0xffffffffu, ke0acc,  off);
        ke1acc  += __shfl_down_sync(0xffffffffu, ke1acc,  off);
    }
    __shared__ float sm[8][5];
    if ((tid & 31) == 0) {
        int w = tid >> 5;
        sm[w][0] = penacc; sm[w][1] = wrkacc; sm[w][2] = stabacc;
        sm[w][3] = ke0acc; sm[w][4] = ke1acc;
    }
    __syncthreads();
    if (tid == 0) {
        float sp = 0.f, sw = 0.f, ss = 0.f, s0v = 0.f, s1v = 0.f;
        #pragma unroll
        for (int w = 0; w < 8; ++w) {
            sp += sm[w][0]; sw += sm[w][1]; ss += sm[w][2];
            s0v += sm[w][3]; s1v += sm[w][4];
        }
        g_pen[blockIdx.x]  = sp;
        g_work[blockIdx.x] = sw;
        g_stab[blockIdx.x] = ss;
        g_ke0[blockIdx.x]  = s0v;
        g_ke1[blockIdx.x]  = s1v;
    }

    // ========== last block: deterministic final reduction ==========
    __threadfence();
    __shared__ int is_last;
    if (tid == 0) {
        unsigned int old = atomicAdd(&g_count, 1u);
        is_last = (old == BLOCKS - 1) ? 1 : 0;
    }
    __syncthreads();
    if (!is_last) return;

    float pen_s = 0.f, wrk_s = 0.f, stab_s = 0.f, k0 = 0.f, k1 = 0.f;
    #pragma unroll
    for (int q = tid; q < BLOCKS; q += 256) {
        pen_s  += g_pen[q];
        wrk_s  += g_work[q];
        stab_s += g_stab[q];
        k0     += g_ke0[q];
        k1     += g_ke1[q];
    }
    #pragma unroll
    for (int off = 16; off > 0; off >>= 1) {
        pen_s  += __shfl_down_sync(0xffffffffu, pen_s,  off);
        wrk_s  += __shfl_down_sync(0xffffffffu, wrk_s,  off);
        stab_s += __shfl_down_sync(0xffffffffu, stab_s, off);
        k0     += __shfl_down_sync(0xffffffffu, k0,     off);
        k1     += __shfl_down_sync(0xffffffffu, k1,     off);
    }
    if ((tid & 31) == 0) {
        int w = tid >> 5;
        sm[w][0] = pen_s; sm[w][1] = wrk_s; sm[w][2] = stab_s;
        sm[w][3] = k0;    sm[w][4] = k1;
    }
    __syncthreads();
    if (tid == 0) {
        float sp = 0.f, sw = 0.f, ss = 0.f, s0v = 0.f, s1v = 0.f;
        #pragma unroll
        for (int w = 0; w < 8; ++w) {
            sp += sm[w][0]; sw += sm[w][1]; ss += sm[w][2];
            s0v += sm[w][3]; s1v += sm[w][4];
        }
        const float pen_loss  = sp / (float)B / ((float)T * (float)N * (float)(N - 1) * 0.5f);
        const float work_mean = sw / (float)(B * (T - 1) * N);
        const float stab_mean = ss / (float)(B * 5 * N);
        const float ks        = s0v / (float)(B * N);
        const float ke_       = s1v / (float)(B * N);
        out[0] = 10.0f * pen_loss + stab_mean + 0.1f * fabsf(ke_ - ks - work_mean);
        g_count = 0u;   // self-reset for next graph replay
    }
}

extern "C" void kernel_launch(void* const* d_in, const int* in_sizes, int n_in,
                              void* d_out, int out_size)
{
    const float* traj = (const float*)d_in[0];
    const float* vel  = (const float*)d_in[1];
    const float* frc  = (const float*)d_in[2];

    fused_kernel<<<BLOCKS, 256>>>(traj, vel, frc, (float*)d_out);
}

// round 10
// speedup vs baseline: 1.1345x; 1.1345x over previous
#include <cuda_runtime.h>
#include <math.h>
#include <stdint.h>

namespace {
constexpr int B = 16, T = 100, N = 128, D = 3;
constexpr int FRAMES = B * T;                 // 1600
constexpr int NIT = 4;                        // frames per block
constexpr int BLOCKS = FRAMES / NIT;          // 400
constexpr int FD = N * D;                     // 384 floats per frame
constexpr int F4 = FD / 4;                    // 96 float4 per frame
constexpr float MIN_DIST = 0.05f;
constexpr float R2 = MIN_DIST * MIN_DIST;     // 0.0025
constexpr int EXT = 192;                      // 128 + 64 wrap replica
}

__device__ float g_pen[BLOCKS];
__device__ float g_work[BLOCKS];
__device__ float g_stab[BLOCKS];
__device__ float g_ke0[BLOCKS];
__device__ float g_ke1[BLOCKS];
__device__ unsigned int g_count;              // zero-init; self-resetting

// volatile LDS.128 — pinned program order defeats ptxas load-sinking
__device__ __forceinline__ float4 lds128(uint32_t a) {
    float4 v;
    asm volatile("ld.shared.v4.f32 {%0,%1,%2,%3}, [%4];"
                 : "=f"(v.x), "=f"(v.y), "=f"(v.z), "=f"(v.w) : "r"(a));
    return v;
}

__global__ __launch_bounds__(256) void fused_kernel(
    const float* __restrict__ traj,
    const float* __restrict__ vel,
    const float* __restrict__ frc,
    float* __restrict__ out)
{
    const int tid = threadIdx.x;
    const int f0  = blockIdx.x * NIT;

    __shared__ __align__(16) float4 sP[NIT][EXT];        // (x,y,z,0)+replica
    __shared__ __align__(16) float  sT[(NIT + 1) * FD];  // raw traj: 5 frames
    __shared__ __align__(16) float  sF[NIT * FD];        // raw frc: 4 frames
    __shared__ __align__(16) float  sV[NIT * FD];        // raw vel: 4 frames

    const int fmod = f0 % T;
    const bool needvel = (fmod == 0) | (fmod == 92) | (fmod == 96);

    // ========== phase 1: single bulk LDG burst (max MLP, incl. vel) ==========
    {
        const float4* t4 = reinterpret_cast<const float4*>(traj);
        const float4* fr4 = reinterpret_cast<const float4*>(frc);
        const float4* v4 = reinterpret_cast<const float4*>(vel);
        float4* dT = reinterpret_cast<float4*>(sT);
        float4* dF = reinterpret_cast<float4*>(sF);
        float4* dV = reinterpret_cast<float4*>(sV);
        const int baseT = f0 * F4;
        const float4 zero = make_float4(0, 0, 0, 0);

        {   // traj: 5 frames = 480 float4 (guard lookahead at global end)
            int idx = tid;
            dT[idx] = (baseT + idx < FRAMES * F4) ? t4[baseT + idx] : zero;
            idx = tid + 256;
            if (idx < (NIT + 1) * F4)
                dT[idx] = (baseT + idx < FRAMES * F4) ? t4[baseT + idx] : zero;
        }
        {   // frc: 4 frames = 384 float4
            dF[tid] = fr4[baseT + tid];
            int idx = tid + 256;
            if (idx < NIT * F4) dF[idx] = fr4[baseT + idx];
        }
        if (needvel) {   // vel: uniform block predicate, same burst
            dV[tid] = v4[baseT + tid];
            int idx = tid + 256;
            if (idx < NIT * F4) dV[idx] = v4[baseT + idx];
        }
    }
    __syncthreads();

    // ========== phase 2: build float4 frames + cheap terms ==========
    float penacc = 0.f, wrkacc = 0.f, stabacc = 0.f, ke0acc = 0.f, ke1acc = 0.f;
    #pragma unroll
    for (int k = 0; k < 2; ++k) {
        const int s  = tid + 256 * k;          // slot 0..511
        const int fl = s >> 7;                 // local frame 0..3
        const int p  = s & 127;                // point index
        const int t  = (f0 + fl) % T;

        const float x = sT[fl * FD + 3 * p];
        const float y = sT[fl * FD + 3 * p + 1];
        const float z = sT[fl * FD + 3 * p + 2];
        float4 v4 = make_float4(x, y, z, 0.f);
        sP[fl][p] = v4;
        if (p < 64) sP[fl][128 + p] = v4;

        if (t < T - 1) {                       // work term from staged data
            const float nx = sT[(fl + 1) * FD + 3 * p];
            const float ny = sT[(fl + 1) * FD + 3 * p + 1];
            const float nz = sT[(fl + 1) * FD + 3 * p + 2];
            const float fx = sF[fl * FD + 3 * p];
            const float fy = sF[fl * FD + 3 * p + 1];
            const float fz = sF[fl * FD + 3 * p + 2];
            wrkacc += fx * (nx - x) + fy * (ny - y) + fz * (nz - z);
        }
        if (t == 0 || t >= T - 5) {            // boundary vel terms (smem-staged)
            const float vx = sV[fl * FD + 3 * p];
            const float vy = sV[fl * FD + 3 * p + 1];
            const float vz = sV[fl * FD + 3 * p + 2];
            const float v2 = vx * vx + vy * vy + vz * vz;
            if (t >= T - 5) {
                stabacc += sqrtf(v2);
                if (t == T - 1) ke1acc += 0.5f * v2;
            } else {
                ke0acc += 0.5f * v2;
            }
        }
    }
    __syncthreads();

    // ========== phase 3: mainloop, double-buffered volatile LDS ==========
    const int i    = tid & 127;
    const int half = tid >> 7;
    const int jb   = 1 + 32 * half;            // first owned j

    #pragma unroll 1
    for (int it = 0; it < NIT; ++it) {
        const float4* P  = sP[it];
        const float4 me  = P[i];
        const uint32_t ca =
            (uint32_t)__cvta_generic_to_shared(P + i + jb);

        float4 q0[4], q1[4];
        float accA = 1e30f, accB = 1e30f;

        #pragma unroll
        for (int e = 0; e < 4; ++e) q0[e] = lds128(ca + 16 * e);

        #pragma unroll
        for (int b = 0; b < 8; ++b) {
            // issue next batch's loads BEFORE current batch's math stalls
            if (b < 7) {
                const uint32_t na = ca + 64 * (b + 1);
                if (b & 1) {
                    #pragma unroll
                    for (int e = 0; e < 4; ++e) q0[e] = lds128(na + 16 * e);
                } else {
                    #pragma unroll
                    for (int e = 0; e < 4; ++e) q1[e] = lds128(na + 16 * e);
                }
            }
            #pragma unroll
            for (int e = 0; e < 4; ++e) {
                const float4 qq = (b & 1) ? q1[e] : q0[e];
                float dx = me.x - qq.x;
                float dy = me.y - qq.y;
                float dz = me.z - qq.z;
                float d2 = dx * dx;
                d2 = fmaf(dy, dy, d2);
                d2 = fmaf(dz, dz, d2);
                if (e & 1) accB = fminf(accB, d2);
                else       accA = fminf(accA, d2);
            }
        }

        // rare exact slow path (identical arithmetic to detection)
        if (fminf(accA, accB) < R2) {
            const float4* C = P + i + jb;
            for (int k = 0; k < 32; ++k) {
                float4 qq = C[k];
                float dx = me.x - qq.x, dy = me.y - qq.y, dz = me.z - qq.z;
                float d2 = dx * dx;
                d2 = fmaf(dy, dy, d2);
                d2 = fmaf(dz, dz, d2);
                if (d2 < R2) {
                    float c = MIN_DIST - sqrtf(d2);
                    penacc += (jb + k == 64) ? 0.5f * c : c;  // j=64 seen twice
                }
            }
        }
    }

    // ========== block reduction of 5 accumulators ==========
    #pragma unroll
    for (int off = 16; off > 0; off >>= 1) {
        penacc  += __shfl_down_sync(0xffffffffu, penacc,  off);
        wrkacc  += __shfl_down_sync(0xffffffffu, wrkacc,  off);
        stabacc += __shfl_down_sync(0xffffffffu, stabacc, off);
        ke0acc  += __shfl_down_sync(0xffffffffu, ke0acc,  off);
        ke1acc  += __shfl_down_sync(0xffffffffu, ke1acc,  off);
    }
    __shared__ float sm[8][5];
    if ((tid & 31) == 0) {
        int w = tid >> 5;
        sm[w][0] = penacc; sm[w][1] = wrkacc; sm[w][2] = stabacc;
        sm[w][3] = ke0acc; sm[w][4] = ke1acc;
    }
    __syncthreads();
    if (tid == 0) {
        float sp = 0.f, sw = 0.f, ss = 0.f, s0v = 0.f, s1v = 0.f;
        #pragma unroll
        for (int w = 0; w < 8; ++w) {
            sp += sm[w][0]; sw += sm[w][1]; ss += sm[w][2];
            s0v += sm[w][3]; s1v += sm[w][4];
        }
        g_pen[blockIdx.x]  = sp;
        g_work[blockIdx.x] = sw;
        g_stab[blockIdx.x] = ss;
        g_ke0[blockIdx.x]  = s0v;
        g_ke1[blockIdx.x]  = s1v;
    }

    // ========== last block: deterministic final reduction ==========
    __threadfence();
    __shared__ int is_last;
    if (tid == 0) {
        unsigned int old = atomicAdd(&g_count, 1u);
        is_last = (old == BLOCKS - 1) ? 1 : 0;
    }
    __syncthreads();
    if (!is_last) return;

    float pen_s = 0.f, wrk_s = 0.f, stab_s = 0.f, k0 = 0.f, k1 = 0.f;
    #pragma unroll
    for (int q = tid; q < BLOCKS; q += 256) {
        pen_s  += g_pen[q];
        wrk_s  += g_work[q];
        stab_s += g_stab[q];
        k0     += g_ke0[q];
        k1     += g_ke1[q];
    }
    #pragma unroll
    for (int off = 16; off > 0; off >>= 1) {
        pen_s  += __shfl_down_sync(0xffffffffu, pen_s,  off);
        wrk_s  += __shfl_down_sync(0xffffffffu, wrk_s,  off);
        stab_s += __shfl_down_sync(0xffffffffu, stab_s, off);
        k0     += __shfl_down_sync(0xffffffffu, k0,     off);
        k1     += __shfl_down_sync(0xffffffffu, k1,     off);
    }
    if ((tid & 31) == 0) {
        int w = tid >> 5;
        sm[w][0] = pen_s; sm[w][1] = wrk_s; sm[w][2] = stab_s;
        sm[w][3] = k0;    sm[w][4] = k1;
    }
    __syncthreads();
    if (tid == 0) {
        float sp = 0.f, sw = 0.f, ss = 0.f, s0v = 0.f, s1v = 0.f;
        #pragma unroll
        for (int w = 0; w < 8; ++w) {
            sp += sm[w][0]; sw += sm[w][1]; ss += sm[w][2];
            s0v += sm[w][3]; s1v += sm[w][4];
        }
        const float pen_loss  = sp / (float)B / ((float)T * (float)N * (float)(N - 1) * 0.5f);
        const float work_mean = sw / (float)(B * (T - 1) * N);
        const float stab_mean = ss / (float)(B * 5 * N);
        const float ks        = s0v / (float)(B * N);
        const float ke_       = s1v / (float)(B * N);
        out[0] = 10.0f * pen_loss + stab_mean + 0.1f * fabsf(ke_ - ks - work_mean);
        g_count = 0u;   // self-reset for next graph replay
    }
}

extern "C" void kernel_launch(void* const* d_in, const int* in_sizes, int n_in,
                              void* d_out, int out_size)
{
    const float* traj = (const float*)d_in[0];
    const float* vel  = (const float*)d_in[1];
    const float* frc  = (const float*)d_in[2];

    fused_kernel<<<BLOCKS, 256>>>(traj, vel, frc, (float*)d_out);
}